// round 2
// baseline (speedup 1.0000x reference)
#include <cuda_runtime.h>
#include <cstdint>

// Problem constants
#define BATCH   128
#define NPTS    2048
#define HID     64
#define NSEG    64
#define ROWS    (BATCH * NPTS)          // 262144
#define AGG_ELEMS (BATCH * NSEG * HID)  // 524288 per layer

// Scratch (allocation-free: __device__ globals)
__device__ float g_h0[(size_t)ROWS * HID];      // 64 MB
__device__ float g_h1[(size_t)ROWS * HID];      // 64 MB
__device__ float g_agg[3 * AGG_ELEMS];          // 6 MB (agg0|agg1|agg2)
__device__ int   g_is64;

// ---------------------------------------------------------------------------
// f32x2 helpers (packed FFMA2 path — 2x fp32 throughput on sm_103a)
// ---------------------------------------------------------------------------
static __device__ __forceinline__ unsigned long long fma2(
    unsigned long long a, unsigned long long b, unsigned long long c) {
  unsigned long long d;
  asm("fma.rn.f32x2 %0, %1, %2, %3;" : "=l"(d) : "l"(a), "l"(b), "l"(c));
  return d;
}
static __device__ __forceinline__ void unpack2(unsigned long long v, float& x, float& y) {
  asm("mov.b64 {%0, %1}, %2;" : "=f"(x), "=f"(y) : "l"(v));
}

// ---------------------------------------------------------------------------
// cluster dtype detection: int64 (odd 32-bit words all zero) vs int32
// ---------------------------------------------------------------------------
__global__ void detect_kernel(const unsigned int* __restrict__ c) {
  if (threadIdx.x == 0) {
    unsigned int o = 0;
#pragma unroll
    for (int i = 0; i < 32; ++i) o |= c[2 * i + 1];
    g_is64 = (o == 0) ? 1 : 0;
  }
}

static __device__ __forceinline__ int load_seg(const void* cl, int row, int is64) {
  return is64 ? (int)((const long long*)cl)[row] : ((const int*)cl)[row];
}

// ---------------------------------------------------------------------------
// zero the agg buffers (0.0f == int 0; atomicMax-as-int on >=0 floats is exact)
// ---------------------------------------------------------------------------
__global__ void zero_kernel(float4* __restrict__ p) {
  int i = blockIdx.x * blockDim.x + threadIdx.x;   // grid sized exactly
  p[i] = make_float4(0.f, 0.f, 0.f, 0.f);
}

// ---------------------------------------------------------------------------
// Fused layer kernel: y = x @ W + b ; LayerNorm ; *g+beta ; ReLU ;
//   [optionally store h] ; atomicMax-scatter into agg (per batch, per segment)
// For K==8   : input = x (row stride 8)
// For K==128 : input row = [h_prev(64) | agg_prev[b, cluster[row]](64)]
//
// Block: 256 threads = 8 warps. Each warp owns 16 rows (4 groups of 4).
// Per lane: output cols (lane, lane+32) packed as one f32x2 accumulator.
// SMEM: sW2 [32][K+2] float2 (paired cols, padded — conflict-free LDS.128)
//       sAd [8 warps][4 rows][K] float2 (A broadcast-duplicated)
// ---------------------------------------------------------------------------
template <int K, bool WRITE_H>
__global__ __launch_bounds__(256) void layer_kernel(
    const float* __restrict__ inA, const float* __restrict__ aggPrev,
    const void* __restrict__ cluster,
    const float* __restrict__ W, const float* __restrict__ bias,
    const float* __restrict__ gamma, const float* __restrict__ beta,
    float* __restrict__ outH, float* __restrict__ aggOut) {
  extern __shared__ char smem_raw[];
  float2* sW2 = (float2*)smem_raw;                                  // 32*(K+2)
  float2* sAd = (float2*)(smem_raw + 32 * (K + 2) * sizeof(float2));

  const int tid = threadIdx.x;
  const int lane = tid & 31;
  const int w = tid >> 5;
  const int is64 = g_is64;

  // Load W paired: sW2[l][k] = {W[k][l], W[k][l+32]}
  for (int idx = tid; idx < 32 * K; idx += 256) {
    int l = idx & 31, k = idx >> 5;
    sW2[l * (K + 2) + k] = make_float2(W[k * 64 + l], W[k * 64 + l + 32]);
  }
  __syncthreads();

  const float2 bv = make_float2(bias[lane],  bias[lane + 32]);
  const float2 gv = make_float2(gamma[lane], gamma[lane + 32]);
  const float2 tv = make_float2(beta[lane],  beta[lane + 32]);

  float2* myA = sAd + (size_t)w * 4 * K;
  const int rowBase = blockIdx.x * 128 + w * 16;
  const char* wrow = (const char*)(sW2 + lane * (K + 2));

  for (int grp = 0; grp < 4; ++grp) {
    const int r0 = rowBase + grp * 4;
    const int batch = r0 >> 11;  // NPTS = 2048 rows per batch

    int seg[4];
#pragma unroll
    for (int r = 0; r < 4; ++r) seg[r] = load_seg(cluster, r0 + r, is64);

    // ---- stage A (duplicated) into SMEM ----
    if (K == 8) {
      if (lane < 8) {
        int r = lane >> 1, j = lane & 1;
        float4 v = *(const float4*)(inA + (size_t)(r0 + r) * 8 + j * 4);
        float2* d = myA + r * K + j * 4;
        d[0] = make_float2(v.x, v.x); d[1] = make_float2(v.y, v.y);
        d[2] = make_float2(v.z, v.z); d[3] = make_float2(v.w, v.w);
      }
    } else {
#pragma unroll
      for (int r = 0; r < 4; ++r) {
        const float* src = (lane < 16)
            ? inA + (size_t)(r0 + r) * 64 + lane * 4
            : aggPrev + ((size_t)(batch * 64 + seg[r])) * 64 + (lane - 16) * 4;
        float4 v = *(const float4*)src;
        float2* d = myA + r * K + lane * 4;
        d[0] = make_float2(v.x, v.x); d[1] = make_float2(v.y, v.y);
        d[2] = make_float2(v.z, v.z); d[3] = make_float2(v.w, v.w);
      }
    }
    __syncwarp();

    // ---- GEMM: acc[r] = sum_k A[r][k] * {W[k][l], W[k][l+32]} ----
    unsigned long long acc[4] = {0ull, 0ull, 0ull, 0ull};
#pragma unroll 8
    for (int k = 0; k < K; k += 4) {
      ulonglong2 w01 = *(const ulonglong2*)(wrow + (size_t)k * 8);
      ulonglong2 w23 = *(const ulonglong2*)(wrow + (size_t)(k + 2) * 8);
#pragma unroll
      for (int r = 0; r < 4; ++r) {
        const ulonglong2* ap = (const ulonglong2*)(myA + r * K + k);
        ulonglong2 a01 = ap[0];
        ulonglong2 a23 = ap[1];
        acc[r] = fma2(a01.x, w01.x, acc[r]);
        acc[r] = fma2(a01.y, w01.y, acc[r]);
        acc[r] = fma2(a23.x, w23.x, acc[r]);
        acc[r] = fma2(a23.y, w23.y, acc[r]);
      }
    }

    // ---- LayerNorm + affine + ReLU + store + scatter-max ----
#pragma unroll
    for (int r = 0; r < 4; ++r) {
      float y0, y1;
      unpack2(acc[r], y0, y1);
      y0 += bv.x; y1 += bv.y;
      float s = y0 + y1;
      float q = y0 * y0 + y1 * y1;
#pragma unroll
      for (int off = 16; off; off >>= 1) {
        s += __shfl_xor_sync(0xffffffffu, s, off);
        q += __shfl_xor_sync(0xffffffffu, q, off);
      }
      float mean = s * 0.015625f;
      float var = fmaf(q, 0.015625f, -mean * mean);
      float rstd = rsqrtf(var + 1e-5f);
      float h0 = fmaxf(fmaf((y0 - mean) * rstd, gv.x, tv.x), 0.f);
      float h1 = fmaxf(fmaf((y1 - mean) * rstd, gv.y, tv.y), 0.f);
      if (WRITE_H) {
        outH[(size_t)(r0 + r) * 64 + lane]      = h0;
        outH[(size_t)(r0 + r) * 64 + lane + 32] = h1;
      }
      int* ab = (int*)(aggOut + ((size_t)(batch * 64 + seg[r])) * 64);
      if (h0 > 0.f) atomicMax(ab + lane,      __float_as_int(h0));
      if (h1 > 0.f) atomicMax(ab + lane + 32, __float_as_int(h1));
    }
    __syncwarp();
  }
}

// ---------------------------------------------------------------------------
// Final: out[b,s,c] = out[b,s,c+64] = agg2[b,s,c] / max(||agg2[b,:,c]||, 1e-12)
// ---------------------------------------------------------------------------
__global__ __launch_bounds__(64) void final_kernel(const float* __restrict__ agg2,
                                                   float* __restrict__ out) {
  const int b = blockIdx.x;
  const int t = threadIdx.x;  // feature 0..63
  const float* a = agg2 + (size_t)b * NSEG * HID;
  float ss = 0.f;
#pragma unroll
  for (int s = 0; s < NSEG; ++s) {
    float v = a[s * HID + t];
    ss = fmaf(v, v, ss);
  }
  float inv = 1.f / fmaxf(sqrtf(ss), 1e-12f);
  float* o = out + (size_t)b * NSEG * 128;
#pragma unroll
  for (int s = 0; s < NSEG; ++s) {
    float v = a[s * HID + t] * inv;
    o[s * 128 + t]      = v;
    o[s * 128 + 64 + t] = v;
  }
}

// ---------------------------------------------------------------------------
extern "C" void kernel_launch(void* const* d_in, const int* in_sizes, int n_in,
                              void* d_out, int out_size) {
  const float* x   = (const float*)d_in[0];
  const void*  cl  = d_in[1];
  const float* W0 = (const float*)d_in[2];
  const float* b0 = (const float*)d_in[3];
  const float* g0 = (const float*)d_in[4];
  const float* t0 = (const float*)d_in[5];
  const float* W1 = (const float*)d_in[6];
  const float* b1 = (const float*)d_in[7];
  const float* g1 = (const float*)d_in[8];
  const float* t1 = (const float*)d_in[9];
  const float* W2 = (const float*)d_in[10];
  const float* b2 = (const float*)d_in[11];
  const float* g2 = (const float*)d_in[12];
  const float* t2 = (const float*)d_in[13];

  void *p_h0 = nullptr, *p_h1 = nullptr, *p_agg = nullptr;
  cudaGetSymbolAddress(&p_h0, g_h0);
  cudaGetSymbolAddress(&p_h1, g_h1);
  cudaGetSymbolAddress(&p_agg, g_agg);
  float* h0   = (float*)p_h0;
  float* h1   = (float*)p_h1;
  float* agg0 = (float*)p_agg;
  float* agg1 = agg0 + AGG_ELEMS;
  float* agg2 = agg0 + 2 * AGG_ELEMS;

  constexpr int SMEM8   = 32 * (8 + 2)   * 8 + 8 * 4 * 8   * 8;  //  4608 B
  constexpr int SMEM128 = 32 * (128 + 2) * 8 + 8 * 4 * 128 * 8;  // 66048 B
  cudaFuncSetAttribute(layer_kernel<128, true>,
                       cudaFuncAttributeMaxDynamicSharedMemorySize, SMEM128);
  cudaFuncSetAttribute(layer_kernel<128, false>,
                       cudaFuncAttributeMaxDynamicSharedMemorySize, SMEM128);

  detect_kernel<<<1, 32>>>((const unsigned int*)cl);
  zero_kernel<<<(3 * AGG_ELEMS) / 4 / 256, 256>>>((float4*)agg0);

  const int blocks = ROWS / 128;  // 2048
  layer_kernel<8, true><<<blocks, 256, SMEM8>>>(
      x, nullptr, cl, W0, b0, g0, t0, h0, agg0);
  layer_kernel<128, true><<<blocks, 256, SMEM128>>>(
      h0, agg0, cl, W1, b1, g1, t1, h1, agg1);
  layer_kernel<128, false><<<blocks, 256, SMEM128>>>(
      h1, agg1, cl, W2, b2, g2, t2, nullptr, agg2);

  final_kernel<<<BATCH, 64>>>(agg2, (float*)d_out);
}

// round 6
// speedup vs baseline: 2.1481x; 2.1481x over previous
#include <cuda_runtime.h>
#include <cstdint>

#define BATCH   128
#define NPTS    2048
#define HID     64
#define NSEG    64
#define ROWS    (BATCH * NPTS)          // 262144
#define AGG_ELEMS (BATCH * NSEG * HID)  // 524288 per layer

// Scratch (allocation-free: __device__ globals)
__device__ float g_h0[(size_t)ROWS * HID];      // 64 MB
__device__ float g_h1[(size_t)ROWS * HID];      // 64 MB
__device__ float g_agg[3 * AGG_ELEMS];          // 6 MB
__device__ float g_P[AGG_ELEMS];                // 2 MB (per-segment partial GEMM)
__device__ int   g_is64;

typedef unsigned long long ull;

static __device__ __forceinline__ ull fma2(ull a, ull b, ull c) {
  ull d;
  asm("fma.rn.f32x2 %0, %1, %2, %3;" : "=l"(d) : "l"(a), "l"(b), "l"(c));
  return d;
}
static __device__ __forceinline__ float u2sum(ull v) {
  return __uint_as_float((unsigned)v) + __uint_as_float((unsigned)(v >> 32));
}

// cluster dtype detection: int64 (odd 32-bit words all zero) vs int32
__global__ void detect_kernel(const unsigned int* __restrict__ c) {
  if (threadIdx.x == 0) {
    unsigned int o = 0;
#pragma unroll
    for (int i = 0; i < 32; ++i) o |= c[2 * i + 1];
    g_is64 = (o == 0) ? 1 : 0;
  }
}
static __device__ __forceinline__ int load_seg(const void* cl, int row, int is64) {
  return is64 ? (int)((const long long*)cl)[row] : ((const int*)cl)[row];
}

__global__ void zero_kernel(float4* __restrict__ p) {
  int i = blockIdx.x * blockDim.x + threadIdx.x;
  p[i] = make_float4(0.f, 0.f, 0.f, 0.f);
}

// ---------------------------------------------------------------------------
// Per-segment partial GEMM: P[b,s,:] = agg[b,s,:] @ Whi + bias
// Whi = rows 64..127 of the layer weight (the gathered-half). grid = BATCH.
// K-packed f32x2 inner loop identical to the main layer kernel.
// ---------------------------------------------------------------------------
__global__ __launch_bounds__(256) void pre_kernel(
    const float* __restrict__ agg, const float* __restrict__ Whi,
    const float* __restrict__ bias, float* __restrict__ P) {
  __shared__ float sW[64 * 68];
  __shared__ float sA[64 * 64];
  const int tid = threadIdx.x, lane = tid & 31, w = tid >> 5;
  const int b = blockIdx.x;

  for (int idx = tid; idx < 4096; idx += 256) {
    int k = idx >> 6, c = idx & 63;
    sW[c * 68 + k] = Whi[idx];
  }
  {
    const float4* src = (const float4*)(agg + (size_t)b * 4096);
    float4* dst = (float4*)sA;
    for (int i = tid; i < 1024; i += 256) dst[i] = src[i];
  }
  __syncthreads();

  const float b0v = bias[lane], b1v = bias[lane + 32];
  const ulonglong2* w0p = (const ulonglong2*)(sW + lane * 68);
  const ulonglong2* w1p = (const ulonglong2*)(sW + (lane + 32) * 68);
  const int r0 = w * 8;

  ull acc[8][2] = {};
#pragma unroll 4
  for (int k4 = 0; k4 < 16; ++k4) {
    ulonglong2 wa = w0p[k4], wb = w1p[k4];
#pragma unroll
    for (int r = 0; r < 8; ++r) {
      ulonglong2 av = *(const ulonglong2*)(sA + (r0 + r) * 64 + 4 * k4);
      acc[r][0] = fma2(av.x, wa.x, acc[r][0]);
      acc[r][0] = fma2(av.y, wa.y, acc[r][0]);
      acc[r][1] = fma2(av.x, wb.x, acc[r][1]);
      acc[r][1] = fma2(av.y, wb.y, acc[r][1]);
    }
  }
#pragma unroll
  for (int r = 0; r < 8; ++r) {
    size_t o = ((size_t)(b << 6) + (r0 + r)) * 64;
    P[o + lane]      = u2sum(acc[r][0]) + b0v;
    P[o + lane + 32] = u2sum(acc[r][1]) + b1v;
  }
}

// ---------------------------------------------------------------------------
// Fused layer: y = A @ W[0:K] (+ bias or + P[b,seg]) ; LN ; *g+beta ; ReLU ;
//   [store h] ; atomicMax scatter into agg.
// Block = 256 thr, 128 rows (contiguous tile). Warp: 16 rows in 2 groups of 8.
// Lane owns cols (lane, lane+32); f32x2 accumulators packed over K.
// SMEM: sW[64][SWS] transposed weights; sA[128][K] (contiguous coalesced copy).
// ---------------------------------------------------------------------------
template <int K, bool WRITE_H, bool HAS_P>
__global__ __launch_bounds__(256) void layer_kernel(
    const float* __restrict__ inA, const float* __restrict__ P,
    const void* __restrict__ cluster,
    const float* __restrict__ W, const float* __restrict__ bias,
    const float* __restrict__ gamma, const float* __restrict__ beta,
    float* __restrict__ outH, float* __restrict__ aggOut) {
  constexpr int SWS = (K == 64) ? 68 : 12;   // padded stride (floats)
  extern __shared__ char smem_raw[];
  float* sW = (float*)smem_raw;                       // 64*SWS
  float* sA = (float*)(smem_raw + 64 * SWS * 4);      // 128*K

  const int tid = threadIdx.x, lane = tid & 31, w = tid >> 5;
  const int is64 = g_is64;
  const int rowBase = blockIdx.x * 128;
  const int batch = rowBase >> 11;

  for (int idx = tid; idx < 64 * K; idx += 256) {
    int k = idx >> 6, c = idx & 63;
    sW[c * SWS + k] = W[idx];
  }
  {
    const float4* src = (const float4*)(inA + (size_t)rowBase * K);
    float4* dst = (float4*)sA;
#pragma unroll
    for (int i = tid; i < 128 * K / 4; i += 256) dst[i] = src[i];
  }
  __syncthreads();

  const float b0v = HAS_P ? 0.f : bias[lane];
  const float b1v = HAS_P ? 0.f : bias[lane + 32];
  const float g0 = gamma[lane], g1 = gamma[lane + 32];
  const float t0 = beta[lane],  t1 = beta[lane + 32];
  const ulonglong2* w0p = (const ulonglong2*)(sW + lane * SWS);
  const ulonglong2* w1p = (const ulonglong2*)(sW + (lane + 32) * SWS);

  for (int grp = 0; grp < 2; ++grp) {
    const int r0 = w * 16 + grp * 8;  // row within block tile

    ull acc[8][2] = {};
#pragma unroll 4
    for (int k4 = 0; k4 < K / 4; ++k4) {
      ulonglong2 wa = w0p[k4], wb = w1p[k4];
#pragma unroll
      for (int r = 0; r < 8; ++r) {
        ulonglong2 av = *(const ulonglong2*)(sA + (r0 + r) * K + 4 * k4);
        acc[r][0] = fma2(av.x, wa.x, acc[r][0]);
        acc[r][0] = fma2(av.y, wa.y, acc[r][0]);
        acc[r][1] = fma2(av.x, wb.x, acc[r][1]);
        acc[r][1] = fma2(av.y, wb.y, acc[r][1]);
      }
    }

    int seg[8];
#pragma unroll
    for (int r = 0; r < 8; ++r) seg[r] = load_seg(cluster, rowBase + r0 + r, is64);
    float p0[8], p1[8];
    if (HAS_P) {
#pragma unroll
      for (int r = 0; r < 8; ++r) {
        size_t o = ((size_t)(batch << 6) + seg[r]) * 64;
        p0[r] = P[o + lane];
        p1[r] = P[o + lane + 32];
      }
    }

#pragma unroll
    for (int r = 0; r < 8; ++r) {
      float y0 = u2sum(acc[r][0]) + (HAS_P ? p0[r] : b0v);
      float y1 = u2sum(acc[r][1]) + (HAS_P ? p1[r] : b1v);
      float s = y0 + y1;
      float q = y0 * y0 + y1 * y1;
#pragma unroll
      for (int off = 16; off; off >>= 1) {
        s += __shfl_xor_sync(0xffffffffu, s, off);
        q += __shfl_xor_sync(0xffffffffu, q, off);
      }
      float mean = s * 0.015625f;
      float var = fmaf(q, 0.015625f, -mean * mean);
      float rstd = rsqrtf(var + 1e-5f);
      float h0 = fmaxf(fmaf((y0 - mean) * rstd, g0, t0), 0.f);
      float h1 = fmaxf(fmaf((y1 - mean) * rstd, g1, t1), 0.f);
      if (WRITE_H) {
        outH[(size_t)(rowBase + r0 + r) * 64 + lane]      = h0;
        outH[(size_t)(rowBase + r0 + r) * 64 + lane + 32] = h1;
      }
      int* ab = (int*)(aggOut + ((size_t)(batch << 6) + seg[r]) * 64);
      if (h0 > 0.f) atomicMax(ab + lane,      __float_as_int(h0));
      if (h1 > 0.f) atomicMax(ab + lane + 32, __float_as_int(h1));
    }
  }
}

// out[b,s,c] = out[b,s,c+64] = agg2[b,s,c] / max(||agg2[b,:,c]||, 1e-12)
__global__ __launch_bounds__(64) void final_kernel(const float* __restrict__ agg2,
                                                   float* __restrict__ out) {
  const int b = blockIdx.x;
  const int t = threadIdx.x;
  const float* a = agg2 + (size_t)b * NSEG * HID;
  float ss = 0.f;
#pragma unroll
  for (int s = 0; s < NSEG; ++s) {
    float v = a[s * HID + t];
    ss = fmaf(v, v, ss);
  }
  float inv = 1.f / fmaxf(sqrtf(ss), 1e-12f);
  float* o = out + (size_t)b * NSEG * 128;
#pragma unroll
  for (int s = 0; s < NSEG; ++s) {
    float v = a[s * HID + t] * inv;
    o[s * 128 + t]      = v;
    o[s * 128 + 64 + t] = v;
  }
}

// ---------------------------------------------------------------------------
extern "C" void kernel_launch(void* const* d_in, const int* in_sizes, int n_in,
                              void* d_out, int out_size) {
  const float* x  = (const float*)d_in[0];
  const void*  cl = d_in[1];
  const float* W0 = (const float*)d_in[2];
  const float* b0 = (const float*)d_in[3];
  const float* g0 = (const float*)d_in[4];
  const float* t0 = (const float*)d_in[5];
  const float* W1 = (const float*)d_in[6];
  const float* b1 = (const float*)d_in[7];
  const float* g1 = (const float*)d_in[8];
  const float* t1 = (const float*)d_in[9];
  const float* W2 = (const float*)d_in[10];
  const float* b2 = (const float*)d_in[11];
  const float* g2 = (const float*)d_in[12];
  const float* t2 = (const float*)d_in[13];

  void *p_h0 = nullptr, *p_h1 = nullptr, *p_agg = nullptr, *p_P = nullptr;
  cudaGetSymbolAddress(&p_h0, g_h0);
  cudaGetSymbolAddress(&p_h1, g_h1);
  cudaGetSymbolAddress(&p_agg, g_agg);
  cudaGetSymbolAddress(&p_P, g_P);
  float* h0buf = (float*)p_h0;
  float* h1buf = (float*)p_h1;
  float* agg0 = (float*)p_agg;
  float* agg1 = agg0 + AGG_ELEMS;
  float* agg2 = agg0 + 2 * AGG_ELEMS;
  float* P    = (float*)p_P;

  constexpr int SMEM_L0 = (64 * 12 + 128 * 8) * 4;    //  7168 B
  constexpr int SMEM_L  = (64 * 68 + 128 * 64) * 4;   // 50176 B
  cudaFuncSetAttribute(layer_kernel<64, true, true>,
                       cudaFuncAttributeMaxDynamicSharedMemorySize, SMEM_L);
  cudaFuncSetAttribute(layer_kernel<64, false, true>,
                       cudaFuncAttributeMaxDynamicSharedMemorySize, SMEM_L);

  detect_kernel<<<1, 32>>>((const unsigned int*)cl);
  zero_kernel<<<(3 * AGG_ELEMS) / 4 / 256, 256>>>((float4*)agg0);

  const int blocks = ROWS / 128;  // 2048
  layer_kernel<8, true, false><<<blocks, 256, SMEM_L0>>>(
      x, nullptr, cl, W0, b0, g0, t0, h0buf, agg0);

  pre_kernel<<<BATCH, 256>>>(agg0, W1 + 64 * 64, b1, P);
  layer_kernel<64, true, true><<<blocks, 256, SMEM_L>>>(
      h0buf, P, cl, W1, b1, g1, t1, h1buf, agg1);

  pre_kernel<<<BATCH, 256>>>(agg1, W2 + 64 * 64, b2, P);
  layer_kernel<64, false, true><<<blocks, 256, SMEM_L>>>(
      h1buf, P, cl, W2, b2, g2, t2, nullptr, agg2);

  final_kernel<<<BATCH, 64>>>(agg2, (float*)d_out);
}

// round 11
// speedup vs baseline: 2.2410x; 1.0433x over previous
#include <cuda_runtime.h>
#include <cstdint>

#define BATCH   128
#define NPTS    2048
#define HID     64
#define NSEG    64
#define ROWS    (BATCH * NPTS)          // 262144
#define AGG_ELEMS (BATCH * NSEG * HID)  // 524288 per layer

__device__ float g_h0[(size_t)ROWS * HID];      // 64 MB
__device__ float g_h1[(size_t)ROWS * HID];      // 64 MB
__device__ float g_agg[3 * AGG_ELEMS];          // 6 MB
__device__ float g_P[AGG_ELEMS];                // 2 MB
__device__ int   g_is64;

typedef unsigned long long ull;

static __device__ __forceinline__ ull fma2(ull a, ull b, ull c) {
  ull d;
  asm("fma.rn.f32x2 %0, %1, %2, %3;" : "=l"(d) : "l"(a), "l"(b), "l"(c));
  return d;
}
static __device__ __forceinline__ float u2sum(ull v) {
  return __uint_as_float((unsigned)v) + __uint_as_float((unsigned)(v >> 32));
}

static __device__ __forceinline__ int load_seg(const void* cl, int row, int is64) {
  return is64 ? (int)((const long long*)cl)[row] : ((const int*)cl)[row];
}

// W SMEM fill: interleaved column-pair layout.
// Row cp (= lane) holds, for each k-pair p: [w(2cp)[2p], w(2cp)[2p+1], w(2cp+1)[2p], w(2cp+1)[2p+1]]
// dest offset = cp*RW + (k>>1)*4 + (c&1)*2 + (k&1)
template <int K, int RW>
static __device__ __forceinline__ void fill_W(float* sW, const float* W, int tid) {
  for (int idx = tid; idx < 64 * K; idx += 256) {
    int k = idx >> 6, c = idx & 63;
    sW[(c >> 1) * RW + (k >> 1) * 4 + (c & 1) * 2 + (k & 1)] = W[idx];
  }
}

// zero agg buffers + detect cluster dtype (keeps launch count so that
// ncu -s 5 -c 1 lands on the layer-2 kernel).
__global__ void init_kernel(float4* __restrict__ p, const unsigned int* __restrict__ c) {
  int i = blockIdx.x * blockDim.x + threadIdx.x;
  p[i] = make_float4(0.f, 0.f, 0.f, 0.f);
  if (i == 0) {
    unsigned int o = 0;
#pragma unroll
    for (int j = 0; j < 32; ++j) o |= c[2 * j + 1];
    g_is64 = (o == 0) ? 1 : 0;
  }
}

// ---------------------------------------------------------------------------
// Per-segment partial GEMM: P[b,s,:] = agg[b,s,:] @ Whi + bias
// grid = 512: blockIdx.x = b*4 + quarter; each block does 16 segment rows.
// RW = 132 floats: row stride 528 B (16B-aligned), bank stride 4 (conflict-free).
// ---------------------------------------------------------------------------
__global__ __launch_bounds__(256) void pre_kernel(
    const float* __restrict__ agg, const float* __restrict__ Whi,
    const float* __restrict__ bias, float* __restrict__ P) {
  __shared__ float sW[32 * 132];
  __shared__ float sA[16 * 64];
  const int tid = threadIdx.x, lane = tid & 31, w = tid >> 5;
  const int b = blockIdx.x >> 2, q = blockIdx.x & 3;

  fill_W<64, 132>(sW, Whi, tid);
  {
    const float4* src = (const float4*)(agg + (size_t)b * 4096 + q * 1024);
    float4* dst = (float4*)sA;
    for (int i = tid; i < 256; i += 256) dst[i] = src[i];
  }
  __syncthreads();

  const float2 bv = *(const float2*)(bias + 2 * lane);
  const float* wp = sW + lane * 132;
  const int r0 = w * 2;

  ull acc[2][2] = {};
#pragma unroll 4
  for (int k4 = 0; k4 < 16; ++k4) {
    ulonglong2 wv0 = *(const ulonglong2*)(wp + 8 * k4);      // pair p=2*k4
    ulonglong2 wv1 = *(const ulonglong2*)(wp + 8 * k4 + 4);  // pair p=2*k4+1
#pragma unroll
    for (int r = 0; r < 2; ++r) {
      ulonglong2 av = *(const ulonglong2*)(sA + (r0 + r) * 64 + 4 * k4);
      acc[r][0] = fma2(av.x, wv0.x, acc[r][0]);
      acc[r][1] = fma2(av.x, wv0.y, acc[r][1]);
      acc[r][0] = fma2(av.y, wv1.x, acc[r][0]);
      acc[r][1] = fma2(av.y, wv1.y, acc[r][1]);
    }
  }
#pragma unroll
  for (int r = 0; r < 2; ++r) {
    size_t o = ((size_t)(b << 6) + (q * 16 + r0 + r)) * 64;
    *(float2*)(P + o + 2 * lane) =
        make_float2(u2sum(acc[r][0]) + bv.x, u2sum(acc[r][1]) + bv.y);
  }
}

// ---------------------------------------------------------------------------
// Fused layer: y = A @ W[0:K] (+ bias or + P[b,seg]) ; LN ; *g+beta ; ReLU ;
//   [store h] ; atomicMax scatter into agg.
// Block = 256 thr, 128 rows. Warp: 16 rows in 2 groups of 8.
// Lane owns cols (2l, 2l+1); f32x2 accumulators packed over K.
// RW: 132 for K=64 (stride 528 B, bank 4); 20 for K=8 (80 B, bank 20) —
// both 16B-aligned for every lane row and LDS.128 conflict-free.
// ---------------------------------------------------------------------------
template <int K, bool WRITE_H, bool HAS_P>
__global__ __launch_bounds__(256) void layer_kernel(
    const float* __restrict__ inA, const float* __restrict__ P,
    const void* __restrict__ cluster,
    const float* __restrict__ W, const float* __restrict__ bias,
    const float* __restrict__ gamma, const float* __restrict__ beta,
    float* __restrict__ outH, float* __restrict__ aggOut) {
  constexpr int RW = (K == 64) ? 132 : 20;
  extern __shared__ char smem_raw[];
  float* sW = (float*)smem_raw;                       // 32*RW
  float* sA = (float*)(smem_raw + 32 * RW * 4);       // 128*K

  const int tid = threadIdx.x, lane = tid & 31, w = tid >> 5;
  const int is64 = g_is64;
  const int rowBase = blockIdx.x * 128;
  const int batch = rowBase >> 11;

  fill_W<K, RW>(sW, W, tid);
  {
    const float4* src = (const float4*)(inA + (size_t)rowBase * K);
    float4* dst = (float4*)sA;
#pragma unroll
    for (int i = tid; i < 128 * K / 4; i += 256) dst[i] = src[i];
  }
  __syncthreads();

  const float2 bv = HAS_P ? make_float2(0.f, 0.f) : *(const float2*)(bias + 2 * lane);
  const float2 gv = *(const float2*)(gamma + 2 * lane);
  const float2 tv = *(const float2*)(beta + 2 * lane);
  const float* wp = sW + lane * RW;

  for (int grp = 0; grp < 2; ++grp) {
    const int r0 = w * 16 + grp * 8;  // row within block tile

    ull acc[8][2] = {};
#pragma unroll 4
    for (int k4 = 0; k4 < K / 4; ++k4) {
      ulonglong2 wv0 = *(const ulonglong2*)(wp + 8 * k4);
      ulonglong2 wv1 = *(const ulonglong2*)(wp + 8 * k4 + 4);
#pragma unroll
      for (int r = 0; r < 8; ++r) {
        ulonglong2 av = *(const ulonglong2*)(sA + (r0 + r) * K + 4 * k4);
        acc[r][0] = fma2(av.x, wv0.x, acc[r][0]);
        acc[r][1] = fma2(av.x, wv0.y, acc[r][1]);
        acc[r][0] = fma2(av.y, wv1.x, acc[r][0]);
        acc[r][1] = fma2(av.y, wv1.y, acc[r][1]);
      }
    }

    int seg[8];
#pragma unroll
    for (int r = 0; r < 8; ++r) seg[r] = load_seg(cluster, rowBase + r0 + r, is64);
    float2 pv[8];
    if (HAS_P) {
#pragma unroll
      for (int r = 0; r < 8; ++r) {
        size_t o = ((size_t)(batch << 6) + seg[r]) * 64;
        pv[r] = *(const float2*)(P + o + 2 * lane);
      }
    }

#pragma unroll
    for (int r = 0; r < 8; ++r) {
      float y0 = u2sum(acc[r][0]) + (HAS_P ? pv[r].x : bv.x);
      float y1 = u2sum(acc[r][1]) + (HAS_P ? pv[r].y : bv.y);
      float s = y0 + y1;
      float q = y0 * y0 + y1 * y1;
#pragma unroll
      for (int off = 16; off; off >>= 1) {
        s += __shfl_xor_sync(0xffffffffu, s, off);
        q += __shfl_xor_sync(0xffffffffu, q, off);
      }
      float mean = s * 0.015625f;
      float var = fmaf(q, 0.015625f, -mean * mean);
      float rstd = rsqrtf(var + 1e-5f);
      float h0 = fmaxf(fmaf((y0 - mean) * rstd, gv.x, tv.x), 0.f);
      float h1 = fmaxf(fmaf((y1 - mean) * rstd, gv.y, tv.y), 0.f);
      if (WRITE_H) {
        *(float2*)(outH + (size_t)(rowBase + r0 + r) * 64 + 2 * lane) =
            make_float2(h0, h1);
      }
      int* ab = (int*)(aggOut + ((size_t)(batch << 6) + seg[r]) * 64);
      if (h0 > 0.f) atomicMax(ab + 2 * lane,     __float_as_int(h0));
      if (h1 > 0.f) atomicMax(ab + 2 * lane + 1, __float_as_int(h1));
    }
  }
}

// out[b,s,c] = out[b,s,c+64] = agg2[b,s,c] / max(||agg2[b,:,c]||, 1e-12)
__global__ __launch_bounds__(64) void final_kernel(const float* __restrict__ agg2,
                                                   float* __restrict__ out) {
  const int b = blockIdx.x;
  const int t = threadIdx.x;
  const float* a = agg2 + (size_t)b * NSEG * HID;
  float ss = 0.f;
#pragma unroll
  for (int s = 0; s < NSEG; ++s) {
    float v = a[s * HID + t];
    ss = fmaf(v, v, ss);
  }
  float inv = 1.f / fmaxf(sqrtf(ss), 1e-12f);
  float* o = out + (size_t)b * NSEG * 128;
#pragma unroll
  for (int s = 0; s < NSEG; ++s) {
    float v = a[s * HID + t] * inv;
    o[s * 128 + t]      = v;
    o[s * 128 + 64 + t] = v;
  }
}

// ---------------------------------------------------------------------------
extern "C" void kernel_launch(void* const* d_in, const int* in_sizes, int n_in,
                              void* d_out, int out_size) {
  const float* x  = (const float*)d_in[0];
  const void*  cl = d_in[1];
  const float* W0 = (const float*)d_in[2];
  const float* b0 = (const float*)d_in[3];
  const float* g0 = (const float*)d_in[4];
  const float* t0 = (const float*)d_in[5];
  const float* W1 = (const float*)d_in[6];
  const float* b1 = (const float*)d_in[7];
  const float* g1 = (const float*)d_in[8];
  const float* t1 = (const float*)d_in[9];
  const float* W2 = (const float*)d_in[10];
  const float* b2 = (const float*)d_in[11];
  const float* g2 = (const float*)d_in[12];
  const float* t2 = (const float*)d_in[13];

  void *p_h0 = nullptr, *p_h1 = nullptr, *p_agg = nullptr, *p_P = nullptr;
  cudaGetSymbolAddress(&p_h0, g_h0);
  cudaGetSymbolAddress(&p_h1, g_h1);
  cudaGetSymbolAddress(&p_agg, g_agg);
  cudaGetSymbolAddress(&p_P, g_P);
  float* h0buf = (float*)p_h0;
  float* h1buf = (float*)p_h1;
  float* agg0 = (float*)p_agg;
  float* agg1 = agg0 + AGG_ELEMS;
  float* agg2 = agg0 + 2 * AGG_ELEMS;
  float* P    = (float*)p_P;

  constexpr int SMEM_L0 = (32 * 20 + 128 * 8) * 4;     //  6656 B
  constexpr int SMEM_L  = (32 * 132 + 128 * 64) * 4;   // 49664 B
  cudaFuncSetAttribute(layer_kernel<64, true, true>,
                       cudaFuncAttributeMaxDynamicSharedMemorySize, SMEM_L);
  cudaFuncSetAttribute(layer_kernel<64, false, true>,
                       cudaFuncAttributeMaxDynamicSharedMemorySize, SMEM_L);

  // Launch order matters for ncu (-s 5 -c 1): 6th launch = layer-2 kernel.
  init_kernel<<<(3 * AGG_ELEMS) / 4 / 256, 256>>>((float4*)agg0,
                                                  (const unsigned int*)cl);

  const int blocks = ROWS / 128;  // 2048
  layer_kernel<8, true, false><<<blocks, 256, SMEM_L0>>>(
      x, nullptr, cl, W0, b0, g0, t0, h0buf, agg0);

  pre_kernel<<<BATCH * 4, 256>>>(agg0, W1 + 64 * 64, b1, P);
  layer_kernel<64, true, true><<<blocks, 256, SMEM_L>>>(
      h0buf, P, cl, W1, b1, g1, t1, h1buf, agg1);

  pre_kernel<<<BATCH * 4, 256>>>(agg1, W2 + 64 * 64, b2, P);
  layer_kernel<64, false, true><<<blocks, 256, SMEM_L>>>(
      h1buf, P, cl, W2, b2, g2, t2, nullptr, agg2);

  final_kernel<<<BATCH, 64>>>(agg2, (float*)d_out);
}